// round 5
// baseline (speedup 1.0000x reference)
#include <cuda_runtime.h>
#include <cstdint>

#define BB 4
#define SS 2048
#define HH 16
#define DH 64

__device__ float g_q[(size_t)8192*1024];
__device__ float g_k[(size_t)8192*1024];
__device__ float g_v[(size_t)8192*1024];
__device__ float g_o[(size_t)8192*1024];

__device__ __forceinline__ uint32_t f2tf(float f){
    uint32_t u; asm("cvt.rna.tf32.f32 %0, %1;" : "=r"(u) : "f"(f)); return u;
}
__device__ __forceinline__ void mma8(float* c, const uint32_t* a, uint32_t b0, uint32_t b1){
    asm volatile("mma.sync.aligned.m16n8k8.row.col.f32.tf32.tf32.f32 "
                 "{%0,%1,%2,%3},{%4,%5,%6,%7},{%8,%9},{%0,%1,%2,%3};"
        : "+f"(c[0]),"+f"(c[1]),"+f"(c[2]),"+f"(c[3])
        : "r"(a[0]),"r"(a[1]),"r"(a[2]),"r"(a[3]),"r"(b0),"r"(b1));
}
__device__ __forceinline__ void ldmx4(uint32_t* r, uint32_t a){
    asm volatile("ldmatrix.sync.aligned.m8n8.x4.shared.b16 {%0,%1,%2,%3}, [%4];"
        : "=r"(r[0]),"=r"(r[1]),"=r"(r[2]),"=r"(r[3]) : "r"(a));
}
__device__ __forceinline__ uint32_t smaddr(const void* p){
    return (uint32_t)__cvta_generic_to_shared(p);
}

// ---------------------------------------------------------------------------
// tf32 GEMM + bias: C[8192,1024] = A * W + bias.  Tile 128x128, BK=16,
// 256 threads = 8 warps (2m x 4n), warp tile 64x32. A-frags via ldmatrix.
// ---------------------------------------------------------------------------
template<bool HEADED>
__global__ __launch_bounds__(256)
void gemm_tf32(const float* __restrict__ A, const float* __restrict__ W,
               const float* __restrict__ bias, float* __restrict__ C)
{
    const int K = 1024, N = 1024;
    __shared__ uint32_t As[128][20];
    __shared__ uint32_t Bs[16][136];
    int tid = threadIdx.x, lane = tid & 31, warp = tid >> 5;
    int wm = warp >> 2, wn = warp & 3;
    int grp = lane >> 2, tig = lane & 3;
    int bn = blockIdx.x, bm = blockIdx.y;

    float acc[4][4][4] = {};

    int ar[2], ac[2], br[2], bc[2];
    #pragma unroll
    for (int i = 0; i < 2; i++){
        int v = tid + i*256;
        ar[i] = v >> 2;  ac[i] = (v & 3) * 4;
        br[i] = v >> 5;  bc[i] = (v & 31) * 4;
    }
    uint32_t a_lm = smaddr(&As[wm*64 + ((lane>>3)&1)*8 + (lane&7)][(lane>>4)*4]);

    float4 pa[2], pb[2];
    #pragma unroll
    for (int i = 0; i < 2; i++){
        pa[i] = *(const float4*)(A + (size_t)(bm*128 + ar[i])*K + ac[i]);
        int n = bn*128 + bc[i];
        const float* wp = HEADED ? (W + ((size_t)(n >> 6)*K + br[i])*64 + (n & 63))
                                 : (W + (size_t)br[i]*N + n);
        pb[i] = *(const float4*)wp;
    }

    for (int kt = 0; kt < K; kt += 16){
        __syncthreads();
        #pragma unroll
        for (int i = 0; i < 2; i++){
            *(uint4*)&As[ar[i]][ac[i]] =
                make_uint4(f2tf(pa[i].x), f2tf(pa[i].y), f2tf(pa[i].z), f2tf(pa[i].w));
            *(uint4*)&Bs[br[i]][bc[i]] =
                make_uint4(f2tf(pb[i].x), f2tf(pb[i].y), f2tf(pb[i].z), f2tf(pb[i].w));
        }
        __syncthreads();
        if (kt + 16 < K){
            #pragma unroll
            for (int i = 0; i < 2; i++){
                pa[i] = *(const float4*)(A + (size_t)(bm*128 + ar[i])*K + (kt+16) + ac[i]);
                int n = bn*128 + bc[i];
                const float* wp = HEADED ? (W + ((size_t)(n >> 6)*K + (kt+16+br[i]))*64 + (n & 63))
                                         : (W + (size_t)(kt+16+br[i])*N + n);
                pb[i] = *(const float4*)wp;
            }
        }
        #pragma unroll
        for (int kc = 0; kc < 2; kc++){
            uint32_t af[4][4];
            #pragma unroll
            for (int mt = 0; mt < 4; mt++)
                ldmx4(af[mt], a_lm + (uint32_t)(mt*16*20 + kc*8)*4);
            #pragma unroll
            for (int nt = 0; nt < 4; nt++){
                uint32_t b0 = Bs[kc*8+tig  ][wn*32 + nt*8 + grp];
                uint32_t b1 = Bs[kc*8+tig+4][wn*32 + nt*8 + grp];
                #pragma unroll
                for (int mt = 0; mt < 4; mt++)
                    mma8(acc[mt][nt], af[mt], b0, b1);
            }
        }
    }

    #pragma unroll
    for (int mt = 0; mt < 4; mt++){
        int row = bm*128 + wm*64 + mt*16 + grp;
        #pragma unroll
        for (int nt = 0; nt < 4; nt++){
            int col = bn*128 + wn*32 + nt*8 + 2*tig;
            float bx = bias[col], by = bias[col+1];
            *(float2*)(C + (size_t)row*N + col) =
                make_float2(acc[mt][nt][0] + bx, acc[mt][nt][1] + by);
            *(float2*)(C + (size_t)(row+8)*N + col) =
                make_float2(acc[mt][nt][2] + bx, acc[mt][nt][3] + by);
        }
    }
}

// ---------------------------------------------------------------------------
// Flash attention, tf32 mma + ldmatrix. Block = 256 threads (8 warps),
// 128 q rows (16/warp). Key tile 32.
//  Ks[32][68]  row=key, col=dh         (QK^T B-frags: straight ldmatrix)
//  Vt[64][36]  row=dh,  col=key        (PV B-frags: straight ldmatrix)
//  Ps[8][16][36] per-warp P            (PV A-frags: straight ldmatrix)
// ---------------------------------------------------------------------------
__global__ __launch_bounds__(256)
void attn_tf32(const float* __restrict__ q, const float* __restrict__ k,
               const float* __restrict__ v, float* __restrict__ o)
{
    __shared__ uint32_t Ks[32][68];
    __shared__ uint32_t Vt[64][36];
    __shared__ uint32_t Ps[8][16][36];
    int tid = threadIdx.x, lane = tid & 31, warp = tid >> 5;
    int grp = lane >> 2, tig = lane & 3;
    int b = blockIdx.z, h = blockIdx.y;
    int qrow = blockIdx.x * 128 + warp * 16;

    uint32_t qf[8][4];
    {
        size_t r0 = ((size_t)(b*SS + qrow + grp    )*HH + h)*DH;
        size_t r1 = ((size_t)(b*SS + qrow + grp + 8)*HH + h)*DH;
        #pragma unroll
        for (int kc = 0; kc < 8; kc++){
            qf[kc][0] = f2tf(q[r0 + kc*8 + tig    ] * 0.125f);
            qf[kc][1] = f2tf(q[r1 + kc*8 + tig    ] * 0.125f);
            qf[kc][2] = f2tf(q[r0 + kc*8 + tig + 4] * 0.125f);
            qf[kc][3] = f2tf(q[r1 + kc*8 + tig + 4] * 0.125f);
        }
    }

    uint32_t ks_lm = smaddr(&Ks[lane & 7][(lane >> 3) * 4]);
    uint32_t vt_lm = smaddr(&Vt[lane & 7][(lane >> 3) * 4]);
    uint32_t ps_lm = smaddr(&Ps[warp][((lane >> 3) & 1) * 8 + (lane & 7)][(lane >> 4) * 4]);

    float oacc[8][4] = {};
    float mrun[2] = {-1e30f, -1e30f}, lrun[2] = {0.f, 0.f};
    const float* kg = k + ((size_t)b*SS*HH + h)*DH;
    const float* vg = v + ((size_t)b*SS*HH + h)*DH;

    int vkey = tid & 31;
    int vdb0 = tid >> 5;

    for (int kt = 0; kt < SS; kt += 32){
        __syncthreads();
        #pragma unroll
        for (int i = 0; i < 2; i++){   // K tile 32x64, coalesced
            int v4 = tid + i*256;
            int r = v4 >> 4, c4 = (v4 & 15)*4;
            float4 t = *(const float4*)(kg + (size_t)(kt + r)*1024 + c4);
            *(uint4*)&Ks[r][c4] = make_uint4(f2tf(t.x), f2tf(t.y), f2tf(t.z), f2tf(t.w));
        }
        #pragma unroll
        for (int i = 0; i < 2; i++){   // V tile -> transposed smem
            int db = vdb0 + 8*i;
            float4 u = *(const float4*)(vg + (size_t)(kt + vkey)*1024 + db*4);
            Vt[db*4 + 0][vkey] = f2tf(u.x);
            Vt[db*4 + 1][vkey] = f2tf(u.y);
            Vt[db*4 + 2][vkey] = f2tf(u.z);
            Vt[db*4 + 3][vkey] = f2tf(u.w);
        }
        __syncthreads();

        // S = Q K^T : 16q x 32 keys per warp
        float sacc[4][4] = {};
        #pragma unroll
        for (int nt = 0; nt < 4; nt++){
            #pragma unroll
            for (int kcp = 0; kcp < 4; kcp++){
                uint32_t kb[4];
                ldmx4(kb, ks_lm + (uint32_t)(nt*8*68 + kcp*16)*4);
                mma8(sacc[nt], qf[2*kcp  ], kb[0], kb[1]);
                mma8(sacc[nt], qf[2*kcp+1], kb[2], kb[3]);
            }
        }

        // online softmax (2 rows per thread)
        #pragma unroll
        for (int rh = 0; rh < 2; rh++){
            float mx = -1e30f;
            #pragma unroll
            for (int nt = 0; nt < 4; nt++)
                mx = fmaxf(mx, fmaxf(sacc[nt][rh*2], sacc[nt][rh*2+1]));
            mx = fmaxf(mx, __shfl_xor_sync(0xffffffffu, mx, 1));
            mx = fmaxf(mx, __shfl_xor_sync(0xffffffffu, mx, 2));
            float mnew = fmaxf(mrun[rh], mx);
            float corr = __expf(mrun[rh] - mnew);
            mrun[rh] = mnew;
            float sum = 0.f;
            #pragma unroll
            for (int nt = 0; nt < 4; nt++){
                float p0 = __expf(sacc[nt][rh*2]   - mnew);
                float p1 = __expf(sacc[nt][rh*2+1] - mnew);
                sacc[nt][rh*2] = p0; sacc[nt][rh*2+1] = p1;
                sum += p0 + p1;
            }
            sum += __shfl_xor_sync(0xffffffffu, sum, 1);
            sum += __shfl_xor_sync(0xffffffffu, sum, 2);
            lrun[rh] = lrun[rh]*corr + sum;
            #pragma unroll
            for (int nt = 0; nt < 8; nt++){
                oacc[nt][rh*2]   *= corr;
                oacc[nt][rh*2+1] *= corr;
            }
        }

        // P -> per-warp smem (tf32)
        #pragma unroll
        for (int nt = 0; nt < 4; nt++){
            *(uint2*)&Ps[warp][grp  ][nt*8 + 2*tig] =
                make_uint2(f2tf(sacc[nt][0]), f2tf(sacc[nt][1]));
            *(uint2*)&Ps[warp][grp+8][nt*8 + 2*tig] =
                make_uint2(f2tf(sacc[nt][2]), f2tf(sacc[nt][3]));
        }
        __syncwarp();

        // O += P V
        uint32_t pa[4][4];
        #pragma unroll
        for (int kc = 0; kc < 4; kc++)
            ldmx4(pa[kc], ps_lm + (uint32_t)(kc*8)*4);
        #pragma unroll
        for (int nt = 0; nt < 8; nt++){
            #pragma unroll
            for (int kcp = 0; kcp < 2; kcp++){
                uint32_t vb[4];
                ldmx4(vb, vt_lm + (uint32_t)(nt*8*36 + kcp*16)*4);
                mma8(oacc[nt], pa[2*kcp  ], vb[0], vb[1]);
                mma8(oacc[nt], pa[2*kcp+1], vb[2], vb[3]);
            }
        }
    }

    float inv0 = 1.f / lrun[0], inv1 = 1.f / lrun[1];
    size_t r0 = ((size_t)(b*SS + qrow + grp    )*HH + h)*DH;
    size_t r1 = ((size_t)(b*SS + qrow + grp + 8)*HH + h)*DH;
    #pragma unroll
    for (int nt = 0; nt < 8; nt++){
        int col = nt*8 + 2*tig;
        *(float2*)(o + r0 + col) = make_float2(oacc[nt][0]*inv0, oacc[nt][1]*inv0);
        *(float2*)(o + r1 + col) = make_float2(oacc[nt][2]*inv1, oacc[nt][3]*inv1);
    }
}

// ---------------------------------------------------------------------------
extern "C" void kernel_launch(void* const* d_in, const int* in_sizes, int n_in,
                              void* d_out, int out_size)
{
    (void)in_sizes; (void)n_in; (void)out_size;
    const float* queries = (const float*)d_in[0];
    const float* keys    = (const float*)d_in[1];
    const float* values  = (const float*)d_in[2];
    const float* Wq = (const float*)d_in[3];
    const float* bq = (const float*)d_in[4];
    const float* Wk = (const float*)d_in[5];
    const float* bk = (const float*)d_in[6];
    const float* Wv = (const float*)d_in[7];
    const float* bv = (const float*)d_in[8];
    const float* Wo = (const float*)d_in[9];
    const float* bo = (const float*)d_in[10];
    float* out = (float*)d_out;

    float *pq, *pk, *pv, *po;
    cudaGetSymbolAddress((void**)&pq, g_q);
    cudaGetSymbolAddress((void**)&pk, g_k);
    cudaGetSymbolAddress((void**)&pv, g_v);
    cudaGetSymbolAddress((void**)&po, g_o);

    dim3 ggrid(8, 64);                 // N/128 x M/128
    gemm_tf32<true><<<ggrid, 256>>>(queries, Wq, bq, pq);
    gemm_tf32<true><<<ggrid, 256>>>(keys,    Wk, bk, pk);
    gemm_tf32<true><<<ggrid, 256>>>(values,  Wv, bv, pv);

    dim3 agrid(SS/128, HH, BB);        // (16, 16, 4)
    attn_tf32<<<agrid, 256>>>(pq, pk, pv, po);

    gemm_tf32<false><<<ggrid, 256>>>(po, Wo, bo, out);
}

// round 7
// speedup vs baseline: 1.1194x; 1.1194x over previous
#include <cuda_runtime.h>
#include <cstdint>

#define BB 4
#define SS 2048
#define HH 16
#define DH 64
#define QSCALE 0.18033688011112042f   // 0.125 * log2(e)

__device__ float g_q[(size_t)8192*1024];
__device__ float g_k[(size_t)8192*1024];
__device__ float g_v[(size_t)8192*1024];
__device__ float g_o[(size_t)8192*1024];

__device__ __forceinline__ uint32_t f2tf(float f){
    uint32_t u; asm("cvt.rna.tf32.f32 %0, %1;" : "=r"(u) : "f"(f)); return u;
}
__device__ __forceinline__ void mma8(float* c, const uint32_t* a, uint32_t b0, uint32_t b1){
    asm volatile("mma.sync.aligned.m16n8k8.row.col.f32.tf32.tf32.f32 "
                 "{%0,%1,%2,%3},{%4,%5,%6,%7},{%8,%9},{%0,%1,%2,%3};"
        : "+f"(c[0]),"+f"(c[1]),"+f"(c[2]),"+f"(c[3])
        : "r"(a[0]),"r"(a[1]),"r"(a[2]),"r"(a[3]),"r"(b0),"r"(b1));
}
__device__ __forceinline__ void ldmx4(uint32_t* r, uint32_t a){
    asm volatile("ldmatrix.sync.aligned.m8n8.x4.shared.b16 {%0,%1,%2,%3}, [%4];"
        : "=r"(r[0]),"=r"(r[1]),"=r"(r[2]),"=r"(r[3]) : "r"(a));
}
__device__ __forceinline__ uint32_t smaddr(const void* p){
    return (uint32_t)__cvta_generic_to_shared(p);
}

// ---------------------------------------------------------------------------
// tf32 GEMM + bias: C[8192,1024] = A * W + bias.  Tile 128x128, BK=16,
// 256 threads = 8 warps (2m x 4n), warp tile 64x32. A-frags via ldmatrix.
// ---------------------------------------------------------------------------
template<bool HEADED>
__global__ __launch_bounds__(256)
void gemm_tf32(const float* __restrict__ A, const float* __restrict__ W,
               const float* __restrict__ bias, float* __restrict__ C)
{
    const int K = 1024, N = 1024;
    __shared__ uint32_t As[128][20];
    __shared__ uint32_t Bs[16][136];
    int tid = threadIdx.x, lane = tid & 31, warp = tid >> 5;
    int wm = warp >> 2, wn = warp & 3;
    int grp = lane >> 2, tig = lane & 3;
    int bn = blockIdx.x, bm = blockIdx.y;

    float acc[4][4][4] = {};

    int ar[2], ac[2], br[2], bc[2];
    #pragma unroll
    for (int i = 0; i < 2; i++){
        int v = tid + i*256;
        ar[i] = v >> 2;  ac[i] = (v & 3) * 4;
        br[i] = v >> 5;  bc[i] = (v & 31) * 4;
    }
    uint32_t a_lm = smaddr(&As[wm*64 + ((lane>>3)&1)*8 + (lane&7)][(lane>>4)*4]);

    float4 pa[2], pb[2];
    #pragma unroll
    for (int i = 0; i < 2; i++){
        pa[i] = *(const float4*)(A + (size_t)(bm*128 + ar[i])*K + ac[i]);
        int n = bn*128 + bc[i];
        const float* wp = HEADED ? (W + ((size_t)(n >> 6)*K + br[i])*64 + (n & 63))
                                 : (W + (size_t)br[i]*N + n);
        pb[i] = *(const float4*)wp;
    }

    for (int kt = 0; kt < K; kt += 16){
        __syncthreads();
        #pragma unroll
        for (int i = 0; i < 2; i++){
            *(uint4*)&As[ar[i]][ac[i]] =
                make_uint4(f2tf(pa[i].x), f2tf(pa[i].y), f2tf(pa[i].z), f2tf(pa[i].w));
            *(uint4*)&Bs[br[i]][bc[i]] =
                make_uint4(f2tf(pb[i].x), f2tf(pb[i].y), f2tf(pb[i].z), f2tf(pb[i].w));
        }
        __syncthreads();
        if (kt + 16 < K){
            #pragma unroll
            for (int i = 0; i < 2; i++){
                pa[i] = *(const float4*)(A + (size_t)(bm*128 + ar[i])*K + (kt+16) + ac[i]);
                int n = bn*128 + bc[i];
                const float* wp = HEADED ? (W + ((size_t)(n >> 6)*K + (kt+16+br[i]))*64 + (n & 63))
                                         : (W + (size_t)(kt+16+br[i])*N + n);
                pb[i] = *(const float4*)wp;
            }
        }
        #pragma unroll
        for (int kc = 0; kc < 2; kc++){
            uint32_t af[4][4];
            #pragma unroll
            for (int mt = 0; mt < 4; mt++)
                ldmx4(af[mt], a_lm + (uint32_t)(mt*16*20 + kc*8)*4);
            #pragma unroll
            for (int nt = 0; nt < 4; nt++){
                uint32_t b0 = Bs[kc*8+tig  ][wn*32 + nt*8 + grp];
                uint32_t b1 = Bs[kc*8+tig+4][wn*32 + nt*8 + grp];
                #pragma unroll
                for (int mt = 0; mt < 4; mt++)
                    mma8(acc[mt][nt], af[mt], b0, b1);
            }
        }
    }

    #pragma unroll
    for (int mt = 0; mt < 4; mt++){
        int row = bm*128 + wm*64 + mt*16 + grp;
        #pragma unroll
        for (int nt = 0; nt < 4; nt++){
            int col = bn*128 + wn*32 + nt*8 + 2*tig;
            float bx = bias[col], by = bias[col+1];
            *(float2*)(C + (size_t)row*N + col) =
                make_float2(acc[mt][nt][0] + bx, acc[mt][nt][1] + by);
            *(float2*)(C + (size_t)(row+8)*N + col) =
                make_float2(acc[mt][nt][2] + bx, acc[mt][nt][3] + by);
        }
    }
}

// ---------------------------------------------------------------------------
// Flash attention, tf32 mma + ldmatrix. Block = 256 threads (8 warps),
// 128 q rows (16/warp). Key tile 32. Capped at 128 regs (2 blocks/SM).
// exp2-based softmax (log2e folded into Q scale).
// ---------------------------------------------------------------------------
__global__ __launch_bounds__(256, 2)
void attn_tf32(const float* __restrict__ q, const float* __restrict__ k,
               const float* __restrict__ v, float* __restrict__ o)
{
    __shared__ uint32_t Ks[32][68];
    __shared__ uint32_t Vt[64][36];
    __shared__ uint32_t Ps[8][16][36];
    int tid = threadIdx.x, lane = tid & 31, warp = tid >> 5;
    int grp = lane >> 2, tig = lane & 3;
    int b = blockIdx.z, h = blockIdx.y;
    int qrow = blockIdx.x * 128 + warp * 16;

    uint32_t qf[8][4];
    {
        size_t r0 = ((size_t)(b*SS + qrow + grp    )*HH + h)*DH;
        size_t r1 = ((size_t)(b*SS + qrow + grp + 8)*HH + h)*DH;
        #pragma unroll
        for (int kc = 0; kc < 8; kc++){
            qf[kc][0] = f2tf(q[r0 + kc*8 + tig    ] * QSCALE);
            qf[kc][1] = f2tf(q[r1 + kc*8 + tig    ] * QSCALE);
            qf[kc][2] = f2tf(q[r0 + kc*8 + tig + 4] * QSCALE);
            qf[kc][3] = f2tf(q[r1 + kc*8 + tig + 4] * QSCALE);
        }
    }

    uint32_t ks_lm = smaddr(&Ks[lane & 7][(lane >> 3) * 4]);
    uint32_t vt_lm = smaddr(&Vt[lane & 7][(lane >> 3) * 4]);
    uint32_t ps_lm = smaddr(&Ps[warp][((lane >> 3) & 1) * 8 + (lane & 7)][(lane >> 4) * 4]);

    float oacc[8][4] = {};
    float mrun[2] = {-1e30f, -1e30f}, lrun[2] = {0.f, 0.f};
    const float* kg = k + ((size_t)b*SS*HH + h)*DH;
    const float* vg = v + ((size_t)b*SS*HH + h)*DH;

    int vkey = tid & 31;
    int vdb0 = tid >> 5;

    for (int kt = 0; kt < SS; kt += 32){
        __syncthreads();
        #pragma unroll
        for (int i = 0; i < 2; i++){   // K tile 32x64, coalesced
            int v4 = tid + i*256;
            int r = v4 >> 4, c4 = (v4 & 15)*4;
            float4 t = *(const float4*)(kg + (size_t)(kt + r)*1024 + c4);
            *(uint4*)&Ks[r][c4] = make_uint4(f2tf(t.x), f2tf(t.y), f2tf(t.z), f2tf(t.w));
        }
        #pragma unroll
        for (int i = 0; i < 2; i++){   // V tile -> transposed smem
            int db = vdb0 + 8*i;
            float4 u = *(const float4*)(vg + (size_t)(kt + vkey)*1024 + db*4);
            Vt[db*4 + 0][vkey] = f2tf(u.x);
            Vt[db*4 + 1][vkey] = f2tf(u.y);
            Vt[db*4 + 2][vkey] = f2tf(u.z);
            Vt[db*4 + 3][vkey] = f2tf(u.w);
        }
        __syncthreads();

        // S' = (Q*0.125*log2e) K^T : 16q x 32 keys per warp
        float sacc[4][4] = {};
        #pragma unroll
        for (int nt = 0; nt < 4; nt++){
            #pragma unroll
            for (int kcp = 0; kcp < 4; kcp++){
                uint32_t kb[4];
                ldmx4(kb, ks_lm + (uint32_t)(nt*8*68 + kcp*16)*4);
                mma8(sacc[nt], qf[2*kcp  ], kb[0], kb[1]);
                mma8(sacc[nt], qf[2*kcp+1], kb[2], kb[3]);
            }
        }

        // online softmax in base 2 (2 rows per thread)
        #pragma unroll
        for (int rh = 0; rh < 2; rh++){
            float mx = -1e30f;
            #pragma unroll
            for (int nt = 0; nt < 4; nt++)
                mx = fmaxf(mx, fmaxf(sacc[nt][rh*2], sacc[nt][rh*2+1]));
            mx = fmaxf(mx, __shfl_xor_sync(0xffffffffu, mx, 1));
            mx = fmaxf(mx, __shfl_xor_sync(0xffffffffu, mx, 2));
            float mnew = fmaxf(mrun[rh], mx);
            float corr = exp2f(mrun[rh] - mnew);
            mrun[rh] = mnew;
            float sum = 0.f;
            #pragma unroll
            for (int nt = 0; nt < 4; nt++){
                float p0 = exp2f(sacc[nt][rh*2]   - mnew);
                float p1 = exp2f(sacc[nt][rh*2+1] - mnew);
                sacc[nt][rh*2] = p0; sacc[nt][rh*2+1] = p1;
                sum += p0 + p1;
            }
            sum += __shfl_xor_sync(0xffffffffu, sum, 1);
            sum += __shfl_xor_sync(0xffffffffu, sum, 2);
            lrun[rh] = lrun[rh]*corr + sum;
            #pragma unroll
            for (int nt = 0; nt < 8; nt++){
                oacc[nt][rh*2]   *= corr;
                oacc[nt][rh*2+1] *= corr;
            }
        }

        // P -> per-warp smem (tf32)
        #pragma unroll
        for (int nt = 0; nt < 4; nt++){
            *(uint2*)&Ps[warp][grp  ][nt*8 + 2*tig] =
                make_uint2(f2tf(sacc[nt][0]), f2tf(sacc[nt][1]));
            *(uint2*)&Ps[warp][grp+8][nt*8 + 2*tig] =
                make_uint2(f2tf(sacc[nt][2]), f2tf(sacc[nt][3]));
        }
        __syncwarp();

        // O += P V
        uint32_t pa[4][4];
        #pragma unroll
        for (int kc = 0; kc < 4; kc++)
            ldmx4(pa[kc], ps_lm + (uint32_t)(kc*8)*4);
        #pragma unroll
        for (int nt = 0; nt < 8; nt++){
            #pragma unroll
            for (int kcp = 0; kcp < 2; kcp++){
                uint32_t vb[4];
                ldmx4(vb, vt_lm + (uint32_t)(nt*8*36 + kcp*16)*4);
                mma8(oacc[nt], pa[2*kcp  ], vb[0], vb[1]);
                mma8(oacc[nt], pa[2*kcp+1], vb[2], vb[3]);
            }
        }
    }

    float inv0 = 1.f / lrun[0], inv1 = 1.f / lrun[1];
    size_t r0 = ((size_t)(b*SS + qrow + grp    )*HH + h)*DH;
    size_t r1 = ((size_t)(b*SS + qrow + grp + 8)*HH + h)*DH;
    #pragma unroll
    for (int nt = 0; nt < 8; nt++){
        int col = nt*8 + 2*tig;
        *(float2*)(o + r0 + col) = make_float2(oacc[nt][0]*inv0, oacc[nt][1]*inv0);
        *(float2*)(o + r1 + col) = make_float2(oacc[nt][2]*inv1, oacc[nt][3]*inv1);
    }
}

// ---------------------------------------------------------------------------
extern "C" void kernel_launch(void* const* d_in, const int* in_sizes, int n_in,
                              void* d_out, int out_size)
{
    (void)in_sizes; (void)n_in; (void)out_size;
    const float* queries = (const float*)d_in[0];
    const float* keys    = (const float*)d_in[1];
    const float* values  = (const float*)d_in[2];
    const float* Wq = (const float*)d_in[3];
    const float* bq = (const float*)d_in[4];
    const float* Wk = (const float*)d_in[5];
    const float* bk = (const float*)d_in[6];
    const float* Wv = (const float*)d_in[7];
    const float* bv = (const float*)d_in[8];
    const float* Wo = (const float*)d_in[9];
    const float* bo = (const float*)d_in[10];
    float* out = (float*)d_out;

    float *pq, *pk, *pv, *po;
    cudaGetSymbolAddress((void**)&pq, g_q);
    cudaGetSymbolAddress((void**)&pk, g_k);
    cudaGetSymbolAddress((void**)&pv, g_v);
    cudaGetSymbolAddress((void**)&po, g_o);

    dim3 ggrid(8, 64);                 // N/128 x M/128
    gemm_tf32<true><<<ggrid, 256>>>(queries, Wq, bq, pq);
    gemm_tf32<true><<<ggrid, 256>>>(keys,    Wk, bk, pk);
    gemm_tf32<true><<<ggrid, 256>>>(values,  Wv, bv, pv);

    dim3 agrid(SS/128, HH, BB);        // (16, 16, 4)
    attn_tf32<<<agrid, 256>>>(pq, pk, pv, po);

    gemm_tf32<false><<<ggrid, 256>>>(po, Wo, bo, out);
}